// round 12
// baseline (speedup 1.0000x reference)
#include <cuda_runtime.h>
#include <cuda_fp16.h>
#include <cstdint>

// ---------------- problem constants ----------------
#define NN 32
#define CCH 128
#define HH 64
#define WW 64
#define NHW_F 131072.0f
#define EPSV 1e-5f

// ---------------- smem layout (byte offsets) ----------------
#define TSTRIDE 272                 // 17x16B segs -> LDSM conflict-free
#define WHI_OFF 0
#define THI0_OFF 34816              // 128*272
#define THI1_OFF 43520              // +32*272
#define XS0_OFF 52224
// XS: 32 channels x 10 rows x 24 floats (halo col h at offset h+3, cols 1..16 16B-aligned)
#define XROW 24
#define XCH  240
#define XSBUF_BYTES (32 * XCH * 4)          // 30720
#define XS1_OFF (XS0_OFF + XSBUF_BYTES)     // 82944
#define RED_OFF (XS1_OFF + XSBUF_BYTES)     // 113664
#define SMEM_BYTES (RED_OFF + 4096)         // 117760

// ---------------- device scratch ----------------
__device__ float g_y1[NN * CCH * HH * WW];
__device__ unsigned char g_wt[65536];       // 2 blocks x 32KB fp16 [o][c]
__device__ float g_stats[4 * CCH];
__device__ float g_sc[4 * CCH];

// ---------------- PTX helpers ----------------
__device__ __forceinline__ uint32_t smem_u32(const void* p) {
    uint32_t a;
    asm("{ .reg .u64 t; cvta.to.shared.u64 t, %1; cvt.u32.u64 %0, t; }" : "=r"(a) : "l"(p));
    return a;
}
__device__ __forceinline__ void ldsm_x4(uint32_t* r, uint32_t a) {
    asm volatile("ldmatrix.sync.aligned.m8n8.x4.shared.b16 {%0,%1,%2,%3}, [%4];"
                 : "=r"(r[0]), "=r"(r[1]), "=r"(r[2]), "=r"(r[3]) : "r"(a));
}
__device__ __forceinline__ void ldsmt_x4(uint32_t* r, uint32_t a) {
    asm volatile("ldmatrix.sync.aligned.m8n8.x4.trans.shared.b16 {%0,%1,%2,%3}, [%4];"
                 : "=r"(r[0]), "=r"(r[1]), "=r"(r[2]), "=r"(r[3]) : "r"(a));
}
__device__ __forceinline__ void mma16816h(float* d, const uint32_t* a, const uint32_t* b) {
    asm volatile("mma.sync.aligned.m16n8k16.row.col.f32.f16.f16.f32 "
                 "{%0,%1,%2,%3}, {%4,%5,%6,%7}, {%8,%9}, {%0,%1,%2,%3};"
                 : "+f"(d[0]), "+f"(d[1]), "+f"(d[2]), "+f"(d[3])
                 : "r"(a[0]), "r"(a[1]), "r"(a[2]), "r"(a[3]), "r"(b[0]), "r"(b[1]));
}
__device__ __forceinline__ void cp_async4(uint32_t dst, const void* src, uint32_t srcsz) {
    asm volatile("cp.async.ca.shared.global [%0], [%1], 4, %2;"
                 :: "r"(dst), "l"(src), "r"(srcsz) : "memory");
}
__device__ __forceinline__ void cp_async16(uint32_t dst, const void* src, uint32_t srcsz) {
    asm volatile("cp.async.cg.shared.global [%0], [%1], 16, %2;"
                 :: "r"(dst), "l"(src), "r"(srcsz) : "memory");
}
#define CP_COMMIT() asm volatile("cp.async.commit_group;" ::: "memory")
#define CP_WAIT0()  asm volatile("cp.async.wait_group 0;" ::: "memory")

// ---------------- prep: pw weights to fp16; zero stats ----------------
__global__ void prep_w(const float* __restrict__ pw1, const float* __restrict__ pw2,
                       unsigned char* __restrict__ wt, float* __restrict__ stats) {
    int idx = blockIdx.x * blockDim.x + threadIdx.x;
    if (idx < 4 * CCH) stats[idx] = 0.f;
    if (idx >= 32768) return;
    int blk = idx >> 14;
    int w = idx & 16383;
    float v = (blk ? pw2 : pw1)[w];
    *(__half*)(wt + (uint32_t)blk * 32768u + (uint32_t)w * 2u) = __float2half_rn(v);
}

// ---------------- fused relu(+BN) -> dw3x3 -> HMMA(fp16) pointwise + stats ----------------
// 512 CTAs x 512 threads; 2 tiles x 4 chunk-stages; cp.async + T double-buffer pipeline:
// phase s: [wait halo(s); barrier] -> issue halo(s+1) -> depthwise(s)->T[s&1]
//          -> MMA(s-1)<-T[(s-1)&1]. Single barrier per phase.
// Halo issue AFTER the barrier: the barrier proves all warps finished phase s-1
// (including reads of XS[(s-1)&1] == XS[(s+1)&1]) before we overwrite it.
template <bool PRE_BN>
__global__ __launch_bounds__(512, 1) void conv_mma(
    const float* __restrict__ in, const float* __restrict__ dww,
    const unsigned char* __restrict__ wt,
    const float* __restrict__ prescale, const float* __restrict__ preshift,
    float* __restrict__ out, float* __restrict__ osum, float* __restrict__ osq)
{
    extern __shared__ char smb[];
    const uint32_t base32 = smem_u32(smb);

    const int tid = threadIdx.x;
    const int wid = tid >> 5;
    const int lane = tid & 31;
    const int n = blockIdx.x >> 4;
    const int sub = blockIdx.x & 15;

    // ---- halo issue for stage s (tile = sub*2 + (s>>2), chunk = s&3) ----
    auto issue_halo = [&](int s) {
        const int tile = sub * 2 + (s >> 2);
        const int th0 = (tile >> 2) * 8;
        const int tw0 = (tile & 3) * 16;
        const int c0 = (s & 3) * 32;
        const uint32_t xsb = base32 + ((s & 1) ? XS1_OFF : XS0_OFF);
        #pragma unroll
        for (int u = 0; u < 3; u++) {
            int i = tid + u * 512;
            if (i < 1280) {
                int c = i / 40, rr = i - c * 40;
                int r = rr >> 2, f = rr & 3;
                int gh = th0 - 1 + r;
                bool ok = (unsigned)gh < (unsigned)HH;
                int ghc = ok ? gh : 0;
                const float* src = in + (((size_t)(n * CCH + c0 + c) * HH + ghc) * WW
                                         + tw0 + 4 * f);
                cp_async16(xsb + (uint32_t)(c * XCH + r * XROW + 4 + 4 * f) * 4u,
                           src, ok ? 16u : 0u);
            }
        }
        #pragma unroll
        for (int u = 0; u < 2; u++) {
            int e = tid + u * 512;
            if (e < 640) {
                int c = e / 20, rr = e - c * 20;
                int r = rr >> 1, side = rr & 1;
                int gh = th0 - 1 + r;
                int gw = side ? (tw0 + 16) : (tw0 - 1);
                bool ok = ((unsigned)gh < (unsigned)HH) && ((unsigned)gw < (unsigned)WW);
                const float* src = ok ? in + (((size_t)(n * CCH + c0 + c) * HH + gh) * WW + gw)
                                      : in;
                cp_async4(xsb + (uint32_t)(c * XCH + r * XROW + (side ? 20 : 3)) * 4u,
                          src, ok ? 4u : 0u);
            }
        }
        CP_COMMIT();
    };

    issue_halo(0);

    // ---- W copy into padded smem (overlaps stage-0 cp.async) ----
    {
        const float4* whi = (const float4*)wt;     // 2048 f4
        #pragma unroll
        for (int u = 0; u < 4; u++) {
            int i = tid + u * 512;
            int o = i >> 4, seg = i & 15;
            uint32_t off = (uint32_t)o * TSTRIDE + (uint32_t)seg * 16u;
            *(float4*)(smb + WHI_OFF + off) = whi[i];
        }
    }

    // ---- preload per-chunk BN scale/shift for this thread's dw channel ----
    const int cl = tid >> 4;           // local channel 0..31
    const int m = tid & 15;
    const int ph = m >> 1, half = m & 1;
    float scs[4], shs[4];
    if (PRE_BN) {
        #pragma unroll
        for (int ch = 0; ch < 4; ch++) {
            scs[ch] = prescale[ch * 32 + cl];
            shs[ch] = preshift[ch * 32 + cl];
        }
    }

    // GEMM per-warp tiling: 32(o) x 32(px)
    const int o0 = (wid & 3) * 32;
    const int p0 = (wid >> 2) * 32;
    const uint32_t aRow = (uint32_t)(o0 + (lane & 15)) * TSTRIDE + (uint32_t)(lane >> 4) * 16u;
    const uint32_t bRow = (uint32_t)(lane & 15) * TSTRIDE + (uint32_t)(p0 + (lane >> 4) * 8) * 2u;
    const uint32_t aHi0 = base32 + WHI_OFF + aRow;
    const uint32_t bT0 = base32 + THI0_OFF + bRow;
    const uint32_t bT1 = base32 + THI1_OFF + bRow;

    float d[2][4][4];
    #pragma unroll
    for (int i = 0; i < 2; i++)
        #pragma unroll
        for (int j = 0; j < 4; j++)
            #pragma unroll
            for (int r = 0; r < 4; r++) d[i][j][r] = 0.f;

    // ---- MMA for chunk chm from T buffer buf ----
    auto do_mma = [&](int chm, int buf) {
        const uint32_t bb = buf ? bT1 : bT0;
        #pragma unroll
        for (int kk2 = 0; kk2 < 2; kk2++) {
            const uint32_t ao = (uint32_t)(chm * 2 + kk2) * 32u;
            const uint32_t bo = (uint32_t)kk2 * (16u * TSTRIDE);
            uint32_t ah[2][4], bh[2][4];
            ldsm_x4(ah[0], aHi0 + ao);
            ldsm_x4(ah[1], aHi0 + ao + 16u * TSTRIDE);
            ldsmt_x4(bh[0], bb + bo);
            ldsmt_x4(bh[1], bb + bo + 32u);
            #pragma unroll
            for (int i = 0; i < 2; i++) {
                #pragma unroll
                for (int j = 0; j < 4; j++) {
                    const uint32_t* bhf = &bh[j >> 1][(j & 1) * 2];
                    mma16816h(d[i][j], ah[i], bhf);
                }
            }
        }
    };

    // ---- epilogue for tile tt: write raw output + per-channel stats; reset accum ----
    auto epilogue = [&](int tt) {
        const int th0e = (tt >> 2) * 8;
        const int tw0e = (tt & 3) * 16;
        const int grp = lane >> 2, tg = lane & 3;
        float* redS = (float*)(smb + RED_OFF);       // 512 floats
        float* redQ = redS + 512;
        #pragma unroll
        for (int i = 0; i < 2; i++) {
            #pragma unroll
            for (int rh = 0; rh < 2; rh++) {
                int o = o0 + i * 16 + grp + rh * 8;
                float sv = 0.f, qv = 0.f;
                #pragma unroll
                for (int j = 0; j < 4; j++) {
                    int px = p0 + j * 8 + tg * 2;
                    float v0 = d[i][j][rh * 2], v1 = d[i][j][rh * 2 + 1];
                    *(float2*)(out + ((size_t)(n * CCH + o) * HH + th0e + (px >> 4)) * WW
                                     + tw0e + (px & 15)) = make_float2(v0, v1);
                    sv += v0 + v1;
                    qv = fmaf(v0, v0, fmaf(v1, v1, qv));
                }
                sv += __shfl_xor_sync(0xffffffffu, sv, 1);
                sv += __shfl_xor_sync(0xffffffffu, sv, 2);
                qv += __shfl_xor_sync(0xffffffffu, qv, 1);
                qv += __shfl_xor_sync(0xffffffffu, qv, 2);
                if (tg == 0) {
                    redS[o * 4 + (wid >> 2)] = sv;
                    redQ[o * 4 + (wid >> 2)] = qv;
                }
            }
        }
        #pragma unroll
        for (int i = 0; i < 2; i++)
            #pragma unroll
            for (int j = 0; j < 4; j++)
                #pragma unroll
                for (int r = 0; r < 4; r++) d[i][j][r] = 0.f;
        __syncthreads();
        if (tid < CCH) {
            atomicAdd(&osum[tid], redS[tid * 4] + redS[tid * 4 + 1]
                                + redS[tid * 4 + 2] + redS[tid * 4 + 3]);
            atomicAdd(&osq[tid], redQ[tid * 4] + redQ[tid * 4 + 1]
                               + redQ[tid * 4 + 2] + redQ[tid * 4 + 3]);
        }
    };

    for (int s = 0; s < 8; s++) {
        const int tile = sub * 2 + (s >> 2);
        const int th0 = (tile >> 2) * 8;
        const int tw0 = (tile & 3) * 16;
        const int ch = s & 3;
        const int c0 = ch * 32;
        float* xs = (float*)(smb + ((s & 1) ? XS1_OFF : XS0_OFF));

        CP_WAIT0();        // halo(s) arrived (only group possibly pending)
        __syncthreads();   // all warps past phase s-1: T[(s-1)&1] written, XS[(s+1)&1] free

        if (s < 7) issue_halo(s + 1);   // safe: past barrier, overwrites XS[(s+1)&1]

        // ---- depthwise(s) with fused relu(+BN) -> T[s&1] ----
        {
            const float* wp = dww + (c0 + cl) * 9;
            float w0 = wp[0], w1 = wp[1], w2 = wp[2], w3 = wp[3], w4 = wp[4],
                  w5 = wp[5], w6 = wp[6], w7 = wp[7], w8 = wp[8];
            const float scv = PRE_BN ? scs[ch] : 1.f;
            const float shv = PRE_BN ? shs[ch] : 0.f;
            const float* xb = xs + cl * XCH + 8 * half;
            float sacc[8];
            #pragma unroll
            for (int j = 0; j < 8; j++) sacc[j] = 0.f;
            #pragma unroll
            for (int r = 0; r < 3; r++) {
                const int gh = th0 - 1 + ph + r;
                const bool rowok = (unsigned)gh < (unsigned)HH;
                if (PRE_BN && !rowok) continue;     // whole row contributes zero
                const float* rp = xb + (ph + r) * XROW;
                float4 A = *(const float4*)(rp);
                float4 B = *(const float4*)(rp + 4);
                float4 C = *(const float4*)(rp + 8);
                float4 D = *(const float4*)(rp + 12);
                float L[16] = {A.x, A.y, A.z, A.w, B.x, B.y, B.z, B.w,
                               C.x, C.y, C.z, C.w, D.x, D.y, D.z, D.w};
                if (PRE_BN) {
                    #pragma unroll
                    for (int j = 0; j < 16; j++)
                        L[j] = fmaxf(fmaf(L[j], scv, shv), 0.f);
                    if (half == 0 && tw0 == 0) L[3] = 0.f;
                    if (half == 1 && tw0 == 48) L[12] = 0.f;
                } else {
                    #pragma unroll
                    for (int j = 0; j < 16; j++)
                        L[j] = fmaxf(L[j], 0.f);                // zfill OOB stays 0
                }
                float wr0 = (r == 0) ? w0 : (r == 1) ? w3 : w6;
                float wr1 = (r == 0) ? w1 : (r == 1) ? w4 : w7;
                float wr2 = (r == 0) ? w2 : (r == 1) ? w5 : w8;
                #pragma unroll
                for (int j = 0; j < 8; j++)
                    sacc[j] = fmaf(wr0, L[3 + j],
                              fmaf(wr1, L[4 + j],
                              fmaf(wr2, L[5 + j], sacc[j])));
            }
            uint32_t hiw[4];
            #pragma unroll
            for (int jp = 0; jp < 4; jp++) {
                __half h0 = __float2half_rn(sacc[2 * jp]);
                __half h1 = __float2half_rn(sacc[2 * jp + 1]);
                hiw[jp] = (uint32_t)__half_as_ushort(h0)
                        | ((uint32_t)__half_as_ushort(h1) << 16);
            }
            uint32_t toff = ((s & 1) ? THI1_OFF : THI0_OFF)
                          + (uint32_t)cl * TSTRIDE + (uint32_t)(32 * ph + 16 * half);
            *(uint4*)(smb + toff) = make_uint4(hiw[0], hiw[1], hiw[2], hiw[3]);
        }

        // ---- MMA(s-1) from T[(s-1)&1] (overlaps depthwise above across warps) ----
        if (s > 0) do_mma((s - 1) & 3, (s - 1) & 1);

        // ---- epilogue tile 0 after MMA(3) (phase 4) ----
        if (s == 4) epilogue(sub * 2);
    }

    // ---- tail: MMA(7) + epilogue tile 1 ----
    __syncthreads();                   // T[1] writes from phase 7 complete
    do_mma(3, 1);
    epilogue(sub * 2 + 1);
}

// ---------------- BN helpers ----------------
__global__ void bn_finalize(const float* __restrict__ sum, const float* __restrict__ sq,
                            const float* __restrict__ gamma, const float* __restrict__ beta,
                            float* __restrict__ scale, float* __restrict__ shift) {
    int c = threadIdx.x;
    float inv = 1.0f / NHW_F;
    float m = sum[c] * inv;
    float v = sq[c] * inv - m * m;
    float sc = gamma[c] * rsqrtf(v + EPSV);
    scale[c] = sc;
    shift[c] = beta[c] - m * sc;
}

__global__ void bn_apply(float* __restrict__ y, const float* __restrict__ scale,
                         const float* __restrict__ shift) {
    const int total4 = (NN * CCH * HH * WW) / 4;
    float4* p = (float4*)y;
    for (int i = blockIdx.x * blockDim.x + threadIdx.x; i < total4;
         i += gridDim.x * blockDim.x) {
        int c = (i >> 10) & (CCH - 1);
        float s = scale[c], t = shift[c];
        float4 v = p[i];
        v.x = fmaf(v.x, s, t); v.y = fmaf(v.y, s, t);
        v.z = fmaf(v.z, s, t); v.w = fmaf(v.w, s, t);
        p[i] = v;
    }
}

// ---------------- launch ----------------
extern "C" void kernel_launch(void* const* d_in, const int* in_sizes, int n_in,
                              void* d_out, int out_size) {
    const float* x      = (const float*)d_in[0];
    const float* dw1_w  = (const float*)d_in[1];
    const float* pw1_w  = (const float*)d_in[2];
    const float* gamma1 = (const float*)d_in[3];
    const float* beta1  = (const float*)d_in[4];
    const float* dw2_w  = (const float*)d_in[5];
    const float* pw2_w  = (const float*)d_in[6];
    const float* gamma2 = (const float*)d_in[7];
    const float* beta2  = (const float*)d_in[8];
    float* out = (float*)d_out;

    float *y1, *stats, *sc;
    unsigned char* wt;
    cudaGetSymbolAddress((void**)&y1, g_y1);
    cudaGetSymbolAddress((void**)&stats, g_stats);
    cudaGetSymbolAddress((void**)&sc, g_sc);
    cudaGetSymbolAddress((void**)&wt, g_wt);

    cudaFuncSetAttribute((const void*)conv_mma<false>,
                         cudaFuncAttributeMaxDynamicSharedMemorySize, SMEM_BYTES);
    cudaFuncSetAttribute((const void*)conv_mma<true>,
                         cudaFuncAttributeMaxDynamicSharedMemorySize, SMEM_BYTES);

    prep_w<<<64, 512>>>(pw1_w, pw2_w, wt, stats);

    conv_mma<false><<<512, 512, SMEM_BYTES>>>(x, dw1_w, wt, nullptr, nullptr,
                                              y1, stats, stats + CCH);
    bn_finalize<<<1, CCH>>>(stats, stats + CCH, gamma1, beta1, sc, sc + CCH);

    conv_mma<true><<<512, 512, SMEM_BYTES>>>(y1, dw2_w, wt + 32768, sc, sc + CCH,
                                             out, stats + 2 * CCH, stats + 3 * CCH);
    bn_finalize<<<1, CCH>>>(stats + 2 * CCH, stats + 3 * CCH, gamma2, beta2,
                            sc + 2 * CCH, sc + 3 * CCH);

    bn_apply<<<2048, 256>>>(out, sc + 2 * CCH, sc + 3 * CCH);
}

// round 13
// speedup vs baseline: 1.0631x; 1.0631x over previous
#include <cuda_runtime.h>
#include <cuda_fp16.h>
#include <cstdint>

// ---------------- problem constants ----------------
#define NN 32
#define CCH 128
#define HH 64
#define WW 64
#define NHW_F 131072.0f
#define EPSV 1e-5f

// ---------------- smem layout (byte offsets) ----------------
#define TSTRIDE 272                 // 17x16B segs -> LDSM conflict-free
#define WHI_OFF 0
#define THI0_OFF 34816              // 128*272
#define THI1_OFF 43520              // +32*272
#define XS0_OFF 52224
// XS: 32 channels x 10 rows x 24 floats (halo col h at offset h+3)
#define XROW 24
#define XCH  240
#define XSBUF_BYTES (32 * XCH * 4)          // 30720
#define XS1_OFF (XS0_OFF + XSBUF_BYTES)     // 82944
#define RED_OFF (XS1_OFF + XSBUF_BYTES)     // 113664
#define SMEM_BYTES (RED_OFF + 2048)         // 115712

// ---------------- device scratch ----------------
__device__ float g_y1[NN * CCH * HH * WW];
__device__ unsigned char g_wt[65536];       // 2 blocks x 32KB fp16 [o][c]
__device__ float g_stats[4 * CCH];
__device__ float g_sc[4 * CCH];

// ---------------- PTX helpers ----------------
__device__ __forceinline__ uint32_t smem_u32(const void* p) {
    uint32_t a;
    asm("{ .reg .u64 t; cvta.to.shared.u64 t, %1; cvt.u32.u64 %0, t; }" : "=r"(a) : "l"(p));
    return a;
}
__device__ __forceinline__ void ldsm_x4(uint32_t* r, uint32_t a) {
    asm volatile("ldmatrix.sync.aligned.m8n8.x4.shared.b16 {%0,%1,%2,%3}, [%4];"
                 : "=r"(r[0]), "=r"(r[1]), "=r"(r[2]), "=r"(r[3]) : "r"(a));
}
__device__ __forceinline__ void ldsmt_x4(uint32_t* r, uint32_t a) {
    asm volatile("ldmatrix.sync.aligned.m8n8.x4.trans.shared.b16 {%0,%1,%2,%3}, [%4];"
                 : "=r"(r[0]), "=r"(r[1]), "=r"(r[2]), "=r"(r[3]) : "r"(a));
}
__device__ __forceinline__ void mma16816h(float* d, const uint32_t* a, const uint32_t* b) {
    asm volatile("mma.sync.aligned.m16n8k16.row.col.f32.f16.f16.f32 "
                 "{%0,%1,%2,%3}, {%4,%5,%6,%7}, {%8,%9}, {%0,%1,%2,%3};"
                 : "+f"(d[0]), "+f"(d[1]), "+f"(d[2]), "+f"(d[3])
                 : "r"(a[0]), "r"(a[1]), "r"(a[2]), "r"(a[3]), "r"(b[0]), "r"(b[1]));
}
__device__ __forceinline__ void cp_async4(uint32_t dst, const void* src, uint32_t srcsz) {
    asm volatile("cp.async.ca.shared.global [%0], [%1], 4, %2;"
                 :: "r"(dst), "l"(src), "r"(srcsz) : "memory");
}
__device__ __forceinline__ void cp_async16(uint32_t dst, const void* src, uint32_t srcsz) {
    asm volatile("cp.async.cg.shared.global [%0], [%1], 16, %2;"
                 :: "r"(dst), "l"(src), "r"(srcsz) : "memory");
}
#define CP_COMMIT() asm volatile("cp.async.commit_group;" ::: "memory")
#define CP_WAIT0()  asm volatile("cp.async.wait_group 0;" ::: "memory")
#define BAR_MMA()   asm volatile("bar.sync 1, 256;" ::: "memory")

// ---------------- prep: pw weights to fp16; zero stats ----------------
__global__ void prep_w(const float* __restrict__ pw1, const float* __restrict__ pw2,
                       unsigned char* __restrict__ wt, float* __restrict__ stats) {
    int idx = blockIdx.x * blockDim.x + threadIdx.x;
    if (idx < 4 * CCH) stats[idx] = 0.f;
    if (idx >= 32768) return;
    int blk = idx >> 14;
    int w = idx & 16383;
    float v = (blk ? pw2 : pw1)[w];
    *(__half*)(wt + (uint32_t)blk * 32768u + (uint32_t)w * 2u) = __float2half_rn(v);
}

// ---------------- fused relu(+BN) -> dw3x3 -> HMMA(fp16) pointwise + stats ----------------
// Warp-specialized: warps 0-7 depthwise producers, warps 8-15 MMA consumers.
// Phase s: [wait halo(s); barrier] -> issue halo(s+1)
//          -> producers: depthwise(s)->T[s&1] | consumers: MMA(s-1)<-T[(s-1)&1]
template <bool PRE_BN>
__global__ __launch_bounds__(512, 1) void conv_mma(
    const float* __restrict__ in, const float* __restrict__ dww,
    const unsigned char* __restrict__ wt,
    const float* __restrict__ prescale, const float* __restrict__ preshift,
    float* __restrict__ out, float* __restrict__ osum, float* __restrict__ osq)
{
    extern __shared__ char smb[];
    const uint32_t base32 = smem_u32(smb);

    const int tid = threadIdx.x;
    const int wid = tid >> 5;
    const int lane = tid & 31;
    const int n = blockIdx.x >> 4;
    const int sub = blockIdx.x & 15;

    // ---- halo issue for stage s (tile = sub*2 + (s>>2), chunk = s&3) ----
    auto issue_halo = [&](int s) {
        const int tile = sub * 2 + (s >> 2);
        const int th0 = (tile >> 2) * 8;
        const int tw0 = (tile & 3) * 16;
        const int c0 = (s & 3) * 32;
        const uint32_t xsb = base32 + ((s & 1) ? XS1_OFF : XS0_OFF);
        #pragma unroll
        for (int u = 0; u < 3; u++) {
            int i = tid + u * 512;
            if (i < 1280) {
                int c = i / 40, rr = i - c * 40;
                int r = rr >> 2, f = rr & 3;
                int gh = th0 - 1 + r;
                bool ok = (unsigned)gh < (unsigned)HH;
                int ghc = ok ? gh : 0;
                const float* src = in + (((size_t)(n * CCH + c0 + c) * HH + ghc) * WW
                                         + tw0 + 4 * f);
                cp_async16(xsb + (uint32_t)(c * XCH + r * XROW + 4 + 4 * f) * 4u,
                           src, ok ? 16u : 0u);
            }
        }
        #pragma unroll
        for (int u = 0; u < 2; u++) {
            int e = tid + u * 512;
            if (e < 640) {
                int c = e / 20, rr = e - c * 20;
                int r = rr >> 1, side = rr & 1;
                int gh = th0 - 1 + r;
                int gw = side ? (tw0 + 16) : (tw0 - 1);
                bool ok = ((unsigned)gh < (unsigned)HH) && ((unsigned)gw < (unsigned)WW);
                const float* src = ok ? in + (((size_t)(n * CCH + c0 + c) * HH + gh) * WW + gw)
                                      : in;
                cp_async4(xsb + (uint32_t)(c * XCH + r * XROW + (side ? 20 : 3)) * 4u,
                          src, ok ? 4u : 0u);
            }
        }
        CP_COMMIT();
    };

    issue_halo(0);

    // ---- W copy into padded smem (overlaps stage-0 cp.async) ----
    {
        const float4* whi = (const float4*)wt;     // 2048 f4
        #pragma unroll
        for (int u = 0; u < 4; u++) {
            int i = tid + u * 512;
            int o = i >> 4, seg = i & 15;
            uint32_t off = (uint32_t)o * TSTRIDE + (uint32_t)seg * 16u;
            *(float4*)(smb + WHI_OFF + off) = whi[i];
        }
    }

    // ---- producer thread mapping: 8 threads/channel, 2 rows x 8 cols each ----
    const int cl = (tid >> 3) & 31;    // channel 0..31 (producers: tid<256)
    const int m = tid & 7;
    const int ph2 = m >> 1;            // row pair 0..3
    const int half = m & 1;            // col half
    float scs[4], shs[4];
    if (PRE_BN) {
        #pragma unroll
        for (int ch = 0; ch < 4; ch++) {
            scs[ch] = prescale[ch * 32 + cl];
            shs[ch] = preshift[ch * 32 + cl];
        }
    }

    // ---- consumer tiling: 8 warps, 32(o) x 64(px) each ----
    const int mw = (wid - 8) & 7;
    const int o0 = (mw & 3) * 32;
    const int pg = mw >> 2;            // px group 0..1
    const int p0 = pg * 64;
    const uint32_t aRow = (uint32_t)(o0 + (lane & 15)) * TSTRIDE + (uint32_t)(lane >> 4) * 16u;
    const uint32_t bRow = (uint32_t)(lane & 15) * TSTRIDE + (uint32_t)(p0 + (lane >> 4) * 8) * 2u;
    const uint32_t aHi0 = base32 + WHI_OFF + aRow;
    const uint32_t bT0 = base32 + THI0_OFF + bRow;
    const uint32_t bT1 = base32 + THI1_OFF + bRow;

    float d[2][8][4];
    #pragma unroll
    for (int i = 0; i < 2; i++)
        #pragma unroll
        for (int j = 0; j < 8; j++)
            #pragma unroll
            for (int r = 0; r < 4; r++) d[i][j][r] = 0.f;

    auto do_mma = [&](int chm, int buf) {
        const uint32_t bb = buf ? bT1 : bT0;
        #pragma unroll
        for (int kk2 = 0; kk2 < 2; kk2++) {
            const uint32_t ao = (uint32_t)(chm * 2 + kk2) * 32u;
            const uint32_t bo = (uint32_t)kk2 * (16u * TSTRIDE);
            uint32_t ah[2][4], bh[4][4];
            ldsm_x4(ah[0], aHi0 + ao);
            ldsm_x4(ah[1], aHi0 + ao + 16u * TSTRIDE);
            #pragma unroll
            for (int g = 0; g < 4; g++) ldsmt_x4(bh[g], bb + bo + (uint32_t)g * 32u);
            #pragma unroll
            for (int i = 0; i < 2; i++)
                #pragma unroll
                for (int g = 0; g < 4; g++)
                    #pragma unroll
                    for (int h = 0; h < 2; h++)
                        mma16816h(d[i][g * 2 + h], ah[i], &bh[g][h * 2]);
        }
    };

    // ---- epilogue (MMA warps only): raw output + stats; uses bar.sync 1,256 ----
    auto epilogue = [&](int tt) {
        const int th0e = (tt >> 2) * 8;
        const int tw0e = (tt & 3) * 16;
        const int grp = lane >> 2, tg = lane & 3;
        float* redS = (float*)(smb + RED_OFF);       // 256 + 256 floats
        float* redQ = redS + 256;
        #pragma unroll
        for (int i = 0; i < 2; i++) {
            #pragma unroll
            for (int rh = 0; rh < 2; rh++) {
                int o = o0 + i * 16 + grp + rh * 8;
                float sv = 0.f, qv = 0.f;
                #pragma unroll
                for (int j = 0; j < 8; j++) {
                    int px = p0 + j * 8 + tg * 2;
                    float v0 = d[i][j][rh * 2], v1 = d[i][j][rh * 2 + 1];
                    *(float2*)(out + ((size_t)(n * CCH + o) * HH + th0e + (px >> 4)) * WW
                                     + tw0e + (px & 15)) = make_float2(v0, v1);
                    sv += v0 + v1;
                    qv = fmaf(v0, v0, fmaf(v1, v1, qv));
                }
                sv += __shfl_xor_sync(0xffffffffu, sv, 1);
                sv += __shfl_xor_sync(0xffffffffu, sv, 2);
                qv += __shfl_xor_sync(0xffffffffu, qv, 1);
                qv += __shfl_xor_sync(0xffffffffu, qv, 2);
                if (tg == 0) {
                    redS[o * 2 + pg] = sv;
                    redQ[o * 2 + pg] = qv;
                }
            }
        }
        #pragma unroll
        for (int i = 0; i < 2; i++)
            #pragma unroll
            for (int j = 0; j < 8; j++)
                #pragma unroll
                for (int r = 0; r < 4; r++) d[i][j][r] = 0.f;
        BAR_MMA();
        int c = tid - 256;
        if (c >= 0 && c < CCH) {
            atomicAdd(&osum[c], redS[c * 2] + redS[c * 2 + 1]);
            atomicAdd(&osq[c], redQ[c * 2] + redQ[c * 2 + 1]);
        }
    };

    for (int s = 0; s < 8; s++) {
        const int tile = sub * 2 + (s >> 2);
        const int th0 = (tile >> 2) * 8;
        const int tw0 = (tile & 3) * 16;
        const int ch = s & 3;
        const int c0 = ch * 32;
        float* xs = (float*)(smb + ((s & 1) ? XS1_OFF : XS0_OFF));

        CP_WAIT0();        // halo(s) arrived
        __syncthreads();   // phase s-1 fully done (T[(s-1)&1] written, XS[(s+1)&1] free)

        if (s < 7) issue_halo(s + 1);

        if (wid < 8) {
            // ---- producer: depthwise(s) 2 rows x 8 cols, fused relu(+BN) -> T[s&1] ----
            const float* wp = dww + (c0 + cl) * 9;
            float w[9];
            #pragma unroll
            for (int k = 0; k < 9; k++) w[k] = wp[k];
            const float scv = PRE_BN ? scs[ch] : 1.f;
            const float shv = PRE_BN ? shs[ch] : 0.f;
            const float* xb = xs + cl * XCH + 8 * half;
            float s0a[8], s1a[8];
            #pragma unroll
            for (int j = 0; j < 8; j++) { s0a[j] = 0.f; s1a[j] = 0.f; }
            #pragma unroll
            for (int ir = 0; ir < 4; ir++) {
                const int lr = 2 * ph2 + ir;       // halo row 0..9
                const int gh = th0 - 1 + lr;
                const bool rowok = (unsigned)gh < (unsigned)HH;
                if (PRE_BN && !rowok) continue;    // OOB row contributes 0
                const float* rp = xb + lr * XROW;
                float4 A = *(const float4*)(rp);
                float4 B = *(const float4*)(rp + 4);
                float4 C = *(const float4*)(rp + 8);
                float4 D = *(const float4*)(rp + 12);
                float L[16] = {A.x, A.y, A.z, A.w, B.x, B.y, B.z, B.w,
                               C.x, C.y, C.z, C.w, D.x, D.y, D.z, D.w};
                if (PRE_BN) {
                    #pragma unroll
                    for (int j = 0; j < 16; j++)
                        L[j] = fmaxf(fmaf(L[j], scv, shv), 0.f);
                    if (half == 0 && tw0 == 0) L[3] = 0.f;     // left border (offset 3)
                    if (half == 1 && tw0 == 48) L[12] = 0.f;   // right border (offset 20)
                } else {
                    #pragma unroll
                    for (int j = 0; j < 16; j++)
                        L[j] = fmaxf(L[j], 0.f);               // zfill OOB stays 0
                }
                if (ir <= 2) {
                    float a0 = w[3 * ir], a1 = w[3 * ir + 1], a2 = w[3 * ir + 2];
                    #pragma unroll
                    for (int j = 0; j < 8; j++)
                        s0a[j] = fmaf(a0, L[3 + j],
                                 fmaf(a1, L[4 + j], fmaf(a2, L[5 + j], s0a[j])));
                }
                if (ir >= 1) {
                    float b0 = w[3 * (ir - 1)], b1 = w[3 * (ir - 1) + 1],
                          b2 = w[3 * (ir - 1) + 2];
                    #pragma unroll
                    for (int j = 0; j < 8; j++)
                        s1a[j] = fmaf(b0, L[3 + j],
                                 fmaf(b1, L[4 + j], fmaf(b2, L[5 + j], s1a[j])));
                }
            }
            uint32_t h0w[4], h1w[4];
            #pragma unroll
            for (int jp = 0; jp < 4; jp++) {
                __half a0 = __float2half_rn(s0a[2 * jp]);
                __half a1 = __float2half_rn(s0a[2 * jp + 1]);
                __half b0 = __float2half_rn(s1a[2 * jp]);
                __half b1 = __float2half_rn(s1a[2 * jp + 1]);
                h0w[jp] = (uint32_t)__half_as_ushort(a0)
                        | ((uint32_t)__half_as_ushort(a1) << 16);
                h1w[jp] = (uint32_t)__half_as_ushort(b0)
                        | ((uint32_t)__half_as_ushort(b1) << 16);
            }
            uint32_t toff = ((s & 1) ? THI1_OFF : THI0_OFF)
                          + (uint32_t)cl * TSTRIDE + (uint32_t)(64 * ph2 + 16 * half);
            *(uint4*)(smb + toff) = make_uint4(h0w[0], h0w[1], h0w[2], h0w[3]);
            *(uint4*)(smb + toff + 32) = make_uint4(h1w[0], h1w[1], h1w[2], h1w[3]);
        } else {
            // ---- consumer: MMA(s-1); epilogue tile 0 after MMA(3) ----
            if (s > 0) do_mma((s - 1) & 3, (s - 1) & 1);
            if (s == 4) epilogue(sub * 2);
        }
    }

    // ---- tail: MMA(7) + epilogue tile 1 (MMA warps) ----
    __syncthreads();                   // T[1] writes from phase 7 complete
    if (wid >= 8) {
        do_mma(3, 1);
        epilogue(sub * 2 + 1);
    }
}

// ---------------- BN helpers ----------------
__global__ void bn_finalize(const float* __restrict__ sum, const float* __restrict__ sq,
                            const float* __restrict__ gamma, const float* __restrict__ beta,
                            float* __restrict__ scale, float* __restrict__ shift) {
    int c = threadIdx.x;
    float inv = 1.0f / NHW_F;
    float m = sum[c] * inv;
    float v = sq[c] * inv - m * m;
    float sc = gamma[c] * rsqrtf(v + EPSV);
    scale[c] = sc;
    shift[c] = beta[c] - m * sc;
}

__global__ void bn_apply(float* __restrict__ y, const float* __restrict__ scale,
                         const float* __restrict__ shift) {
    const int total4 = (NN * CCH * HH * WW) / 4;
    float4* p = (float4*)y;
    for (int i = blockIdx.x * blockDim.x + threadIdx.x; i < total4;
         i += gridDim.x * blockDim.x) {
        int c = (i >> 10) & (CCH - 1);
        float s = scale[c], t = shift[c];
        float4 v = p[i];
        v.x = fmaf(v.x, s, t); v.y = fmaf(v.y, s, t);
        v.z = fmaf(v.z, s, t); v.w = fmaf(v.w, s, t);
        p[i] = v;
    }
}

// ---------------- launch ----------------
extern "C" void kernel_launch(void* const* d_in, const int* in_sizes, int n_in,
                              void* d_out, int out_size) {
    const float* x      = (const float*)d_in[0];
    const float* dw1_w  = (const float*)d_in[1];
    const float* pw1_w  = (const float*)d_in[2];
    const float* gamma1 = (const float*)d_in[3];
    const float* beta1  = (const float*)d_in[4];
    const float* dw2_w  = (const float*)d_in[5];
    const float* pw2_w  = (const float*)d_in[6];
    const float* gamma2 = (const float*)d_in[7];
    const float* beta2  = (const float*)d_in[8];
    float* out = (float*)d_out;

    float *y1, *stats, *sc;
    unsigned char* wt;
    cudaGetSymbolAddress((void**)&y1, g_y1);
    cudaGetSymbolAddress((void**)&stats, g_stats);
    cudaGetSymbolAddress((void**)&sc, g_sc);
    cudaGetSymbolAddress((void**)&wt, g_wt);

    cudaFuncSetAttribute((const void*)conv_mma<false>,
                         cudaFuncAttributeMaxDynamicSharedMemorySize, SMEM_BYTES);
    cudaFuncSetAttribute((const void*)conv_mma<true>,
                         cudaFuncAttributeMaxDynamicSharedMemorySize, SMEM_BYTES);

    prep_w<<<64, 512>>>(pw1_w, pw2_w, wt, stats);

    conv_mma<false><<<512, 512, SMEM_BYTES>>>(x, dw1_w, wt, nullptr, nullptr,
                                              y1, stats, stats + CCH);
    bn_finalize<<<1, CCH>>>(stats, stats + CCH, gamma1, beta1, sc, sc + CCH);

    conv_mma<true><<<512, 512, SMEM_BYTES>>>(y1, dw2_w, wt + 32768, sc, sc + CCH,
                                             out, stats + 2 * CCH, stats + 3 * CCH);
    bn_finalize<<<1, CCH>>>(stats + 2 * CCH, stats + 3 * CCH, gamma2, beta2,
                            sc + 2 * CCH, sc + 3 * CCH);

    bn_apply<<<2048, 256>>>(out, sc + 2 * CCH, sc + 3 * CCH);
}

// round 14
// speedup vs baseline: 1.3230x; 1.2445x over previous
#include <cuda_runtime.h>
#include <cuda_fp16.h>
#include <cstdint>

// ---------------- problem constants ----------------
#define NN 32
#define CCH 128
#define HH 64
#define WW 64
#define NHW_F 131072.0f
#define EPSV 1e-5f
#define GRID 148                    // persistent CTAs (1 per SM)
#define NTILES_TOTAL 1024           // 32 images x 32 tiles

// ---------------- smem layout (byte offsets) ----------------
#define TSTRIDE 272                 // 17x16B segs -> LDSM conflict-free
#define WHI_OFF 0
#define THI0_OFF 34816              // 128*272
#define THI1_OFF 43520              // +32*272
#define XS0_OFF 52224
// XS: 32 channels x 10 rows x 24 floats (halo col h at offset h+3)
#define XROW 24
#define XCH  240
#define XSBUF_BYTES (32 * XCH * 4)          // 30720
#define XS1_OFF (XS0_OFF + XSBUF_BYTES)     // 82944
#define RED_OFF (XS1_OFF + XSBUF_BYTES)     // 113664
#define SMEM_BYTES (RED_OFF + 2048)         // 115712

// ---------------- device scratch ----------------
__device__ float g_y1[NN * CCH * HH * WW];
__device__ unsigned char g_wt[65536];       // 2 blocks x 32KB fp16 [o][c]
__device__ float g_stats[4 * CCH];
__device__ float g_sc[4 * CCH];

// ---------------- PTX helpers ----------------
__device__ __forceinline__ uint32_t smem_u32(const void* p) {
    uint32_t a;
    asm("{ .reg .u64 t; cvta.to.shared.u64 t, %1; cvt.u32.u64 %0, t; }" : "=r"(a) : "l"(p));
    return a;
}
__device__ __forceinline__ void ldsm_x4(uint32_t* r, uint32_t a) {
    asm volatile("ldmatrix.sync.aligned.m8n8.x4.shared.b16 {%0,%1,%2,%3}, [%4];"
                 : "=r"(r[0]), "=r"(r[1]), "=r"(r[2]), "=r"(r[3]) : "r"(a));
}
__device__ __forceinline__ void ldsmt_x4(uint32_t* r, uint32_t a) {
    asm volatile("ldmatrix.sync.aligned.m8n8.x4.trans.shared.b16 {%0,%1,%2,%3}, [%4];"
                 : "=r"(r[0]), "=r"(r[1]), "=r"(r[2]), "=r"(r[3]) : "r"(a));
}
__device__ __forceinline__ void mma16816h(float* d, const uint32_t* a, const uint32_t* b) {
    asm volatile("mma.sync.aligned.m16n8k16.row.col.f32.f16.f16.f32 "
                 "{%0,%1,%2,%3}, {%4,%5,%6,%7}, {%8,%9}, {%0,%1,%2,%3};"
                 : "+f"(d[0]), "+f"(d[1]), "+f"(d[2]), "+f"(d[3])
                 : "r"(a[0]), "r"(a[1]), "r"(a[2]), "r"(a[3]), "r"(b[0]), "r"(b[1]));
}
__device__ __forceinline__ void cp_async4(uint32_t dst, const void* src, uint32_t srcsz) {
    asm volatile("cp.async.ca.shared.global [%0], [%1], 4, %2;"
                 :: "r"(dst), "l"(src), "r"(srcsz) : "memory");
}
__device__ __forceinline__ void cp_async16(uint32_t dst, const void* src, uint32_t srcsz) {
    asm volatile("cp.async.cg.shared.global [%0], [%1], 16, %2;"
                 :: "r"(dst), "l"(src), "r"(srcsz) : "memory");
}
#define CP_COMMIT() asm volatile("cp.async.commit_group;" ::: "memory")
#define CP_WAIT0()  asm volatile("cp.async.wait_group 0;" ::: "memory")
#define BAR_MMA()   asm volatile("bar.sync 1, 256;" ::: "memory")

// ---------------- prep: pw weights to fp16; zero stats ----------------
__global__ void prep_w(const float* __restrict__ pw1, const float* __restrict__ pw2,
                       unsigned char* __restrict__ wt, float* __restrict__ stats) {
    int idx = blockIdx.x * blockDim.x + threadIdx.x;
    if (idx < 4 * CCH) stats[idx] = 0.f;
    if (idx >= 32768) return;
    int blk = idx >> 14;
    int w = idx & 16383;
    float v = (blk ? pw2 : pw1)[w];
    *(__half*)(wt + (uint32_t)blk * 32768u + (uint32_t)w * 2u) = __float2half_rn(v);
}

// ---------------- fused relu(+BN) -> dw3x3 -> HMMA(fp16) pointwise + stats ----------------
// Persistent: 148 CTAs, CTA bx owns tiles bx, bx+148, ... (6 or 7 tiles).
// Warp-specialized: warps 0-7 depthwise producers, warps 8-15 MMA consumers.
// Phase s: [wait halo(s); barrier] -> issue halo(s+1)
//          -> producers: depthwise(s)->T[s&1] | consumers: MMA(s-1)<-T[(s-1)&1];
//            epilogue(tile k) fires in phase 4k+4 right after MMA of its chunk 3.
template <bool PRE_BN>
__global__ __launch_bounds__(512, 1) void conv_mma(
    const float* __restrict__ in, const float* __restrict__ dww,
    const unsigned char* __restrict__ wt,
    const float* __restrict__ prescale, const float* __restrict__ preshift,
    float* __restrict__ out, float* __restrict__ osum, float* __restrict__ osq)
{
    extern __shared__ char smb[];
    const uint32_t base32 = smem_u32(smb);

    const int tid = threadIdx.x;
    const int wid = tid >> 5;
    const int lane = tid & 31;
    const int bx = blockIdx.x;
    const int ntiles = (NTILES_TOTAL - bx + GRID - 1) / GRID;
    const int smax = ntiles * 4;

    // ---- halo issue for stage s (tile = bx + (s>>2)*GRID, chunk = s&3) ----
    auto issue_halo = [&](int s) {
        const int t = bx + (s >> 2) * GRID;
        const int n = t >> 5;
        const int tl = t & 31;
        const int th0 = (tl >> 2) * 8;
        const int tw0 = (tl & 3) * 16;
        const int c0 = (s & 3) * 32;
        const uint32_t xsb = base32 + ((s & 1) ? XS1_OFF : XS0_OFF);
        #pragma unroll
        for (int u = 0; u < 3; u++) {
            int i = tid + u * 512;
            if (i < 1280) {
                int c = i / 40, rr = i - c * 40;
                int r = rr >> 2, f = rr & 3;
                int gh = th0 - 1 + r;
                bool ok = (unsigned)gh < (unsigned)HH;
                int ghc = ok ? gh : 0;
                const float* src = in + (((size_t)(n * CCH + c0 + c) * HH + ghc) * WW
                                         + tw0 + 4 * f);
                cp_async16(xsb + (uint32_t)(c * XCH + r * XROW + 4 + 4 * f) * 4u,
                           src, ok ? 16u : 0u);
            }
        }
        #pragma unroll
        for (int u = 0; u < 2; u++) {
            int e = tid + u * 512;
            if (e < 640) {
                int c = e / 20, rr = e - c * 20;
                int r = rr >> 1, side = rr & 1;
                int gh = th0 - 1 + r;
                int gw = side ? (tw0 + 16) : (tw0 - 1);
                bool ok = ((unsigned)gh < (unsigned)HH) && ((unsigned)gw < (unsigned)WW);
                const float* src = ok ? in + (((size_t)(n * CCH + c0 + c) * HH + gh) * WW + gw)
                                      : in;
                cp_async4(xsb + (uint32_t)(c * XCH + r * XROW + (side ? 20 : 3)) * 4u,
                          src, ok ? 4u : 0u);
            }
        }
        CP_COMMIT();
    };

    issue_halo(0);

    // ---- W copy into padded smem (once per CTA; overlaps stage-0 cp.async) ----
    {
        const float4* whi = (const float4*)wt;     // 2048 f4
        #pragma unroll
        for (int u = 0; u < 4; u++) {
            int i = tid + u * 512;
            int o = i >> 4, seg = i & 15;
            uint32_t off = (uint32_t)o * TSTRIDE + (uint32_t)seg * 16u;
            *(float4*)(smb + WHI_OFF + off) = whi[i];
        }
    }

    // ---- producer mapping: 8 threads/channel, 2 rows x 8 cols each ----
    const int cl = (tid >> 3) & 31;
    const int m = tid & 7;
    const int ph2 = m >> 1;
    const int half = m & 1;
    float scs[4], shs[4];
    if (PRE_BN) {
        #pragma unroll
        for (int ch = 0; ch < 4; ch++) {
            scs[ch] = prescale[ch * 32 + cl];
            shs[ch] = preshift[ch * 32 + cl];
        }
    }

    // ---- consumer tiling: 8 warps, 32(o) x 64(px) each ----
    const int mw = (wid - 8) & 7;
    const int o0 = (mw & 3) * 32;
    const int pg = mw >> 2;
    const int p0 = pg * 64;
    const uint32_t aRow = (uint32_t)(o0 + (lane & 15)) * TSTRIDE + (uint32_t)(lane >> 4) * 16u;
    const uint32_t bRow = (uint32_t)(lane & 15) * TSTRIDE + (uint32_t)(p0 + (lane >> 4) * 8) * 2u;
    const uint32_t aHi0 = base32 + WHI_OFF + aRow;
    const uint32_t bT0 = base32 + THI0_OFF + bRow;
    const uint32_t bT1 = base32 + THI1_OFF + bRow;

    float d[2][8][4];
    #pragma unroll
    for (int i = 0; i < 2; i++)
        #pragma unroll
        for (int j = 0; j < 8; j++)
            #pragma unroll
            for (int r = 0; r < 4; r++) d[i][j][r] = 0.f;

    auto do_mma = [&](int chm, int buf) {
        const uint32_t bb = buf ? bT1 : bT0;
        #pragma unroll
        for (int kk2 = 0; kk2 < 2; kk2++) {
            const uint32_t ao = (uint32_t)(chm * 2 + kk2) * 32u;
            const uint32_t bo = (uint32_t)kk2 * (16u * TSTRIDE);
            uint32_t ah[2][4], bh[4][4];
            ldsm_x4(ah[0], aHi0 + ao);
            ldsm_x4(ah[1], aHi0 + ao + 16u * TSTRIDE);
            #pragma unroll
            for (int g = 0; g < 4; g++) ldsmt_x4(bh[g], bb + bo + (uint32_t)g * 32u);
            #pragma unroll
            for (int i = 0; i < 2; i++)
                #pragma unroll
                for (int g = 0; g < 4; g++)
                    #pragma unroll
                    for (int h = 0; h < 2; h++)
                        mma16816h(d[i][g * 2 + h], ah[i], &bh[g][h * 2]);
        }
    };

    // ---- epilogue for owned tile k (MMA warps only) ----
    auto epilogue = [&](int k) {
        const int t = bx + k * GRID;
        const int n = t >> 5;
        const int tl = t & 31;
        const int th0e = (tl >> 2) * 8;
        const int tw0e = (tl & 3) * 16;
        const int grp = lane >> 2, tg = lane & 3;
        float* redS = (float*)(smb + RED_OFF);       // 256 + 256 floats
        float* redQ = redS + 256;
        #pragma unroll
        for (int i = 0; i < 2; i++) {
            #pragma unroll
            for (int rh = 0; rh < 2; rh++) {
                int o = o0 + i * 16 + grp + rh * 8;
                float sv = 0.f, qv = 0.f;
                #pragma unroll
                for (int j = 0; j < 8; j++) {
                    int px = p0 + j * 8 + tg * 2;
                    float v0 = d[i][j][rh * 2], v1 = d[i][j][rh * 2 + 1];
                    *(float2*)(out + ((size_t)(n * CCH + o) * HH + th0e + (px >> 4)) * WW
                                     + tw0e + (px & 15)) = make_float2(v0, v1);
                    sv += v0 + v1;
                    qv = fmaf(v0, v0, fmaf(v1, v1, qv));
                }
                sv += __shfl_xor_sync(0xffffffffu, sv, 1);
                sv += __shfl_xor_sync(0xffffffffu, sv, 2);
                qv += __shfl_xor_sync(0xffffffffu, qv, 1);
                qv += __shfl_xor_sync(0xffffffffu, qv, 2);
                if (tg == 0) {
                    redS[o * 2 + pg] = sv;
                    redQ[o * 2 + pg] = qv;
                }
            }
        }
        #pragma unroll
        for (int i = 0; i < 2; i++)
            #pragma unroll
            for (int j = 0; j < 8; j++)
                #pragma unroll
                for (int r = 0; r < 4; r++) d[i][j][r] = 0.f;
        BAR_MMA();
        int c = tid - 256;
        if (c >= 0 && c < CCH) {
            atomicAdd(&osum[c], redS[c * 2] + redS[c * 2 + 1]);
            atomicAdd(&osq[c], redQ[c * 2] + redQ[c * 2 + 1]);
        }
    };

    for (int s = 0; s < smax; s++) {
        const int t = bx + (s >> 2) * GRID;
        const int tl = t & 31;
        const int th0 = (tl >> 2) * 8;
        const int tw0 = (tl & 3) * 16;
        const int ch = s & 3;
        const int c0 = ch * 32;
        float* xs = (float*)(smb + ((s & 1) ? XS1_OFF : XS0_OFF));

        CP_WAIT0();        // halo(s) arrived
        __syncthreads();   // phase s-1 fully done (T[(s-1)&1] written, XS[(s+1)&1] free)

        if (s + 1 < smax) issue_halo(s + 1);

        if (wid < 8) {
            // ---- producer: depthwise(s) 2 rows x 8 cols, fused relu(+BN) -> T[s&1] ----
            const float* wp = dww + (c0 + cl) * 9;
            float w[9];
            #pragma unroll
            for (int k = 0; k < 9; k++) w[k] = wp[k];
            const float scv = PRE_BN ? scs[ch] : 1.f;
            const float shv = PRE_BN ? shs[ch] : 0.f;
            const float* xb = xs + cl * XCH + 8 * half;
            float s0a[8], s1a[8];
            #pragma unroll
            for (int j = 0; j < 8; j++) { s0a[j] = 0.f; s1a[j] = 0.f; }
            #pragma unroll
            for (int ir = 0; ir < 4; ir++) {
                const int lr = 2 * ph2 + ir;       // halo row 0..9
                const int gh = th0 - 1 + lr;
                const bool rowok = (unsigned)gh < (unsigned)HH;
                if (PRE_BN && !rowok) continue;    // OOB row contributes 0
                const float* rp = xb + lr * XROW;
                float4 A = *(const float4*)(rp);
                float4 B = *(const float4*)(rp + 4);
                float4 C = *(const float4*)(rp + 8);
                float4 D = *(const float4*)(rp + 12);
                float L[16] = {A.x, A.y, A.z, A.w, B.x, B.y, B.z, B.w,
                               C.x, C.y, C.z, C.w, D.x, D.y, D.z, D.w};
                if (PRE_BN) {
                    #pragma unroll
                    for (int j = 0; j < 16; j++)
                        L[j] = fmaxf(fmaf(L[j], scv, shv), 0.f);
                    if (half == 0 && tw0 == 0) L[3] = 0.f;     // left border
                    if (half == 1 && tw0 == 48) L[12] = 0.f;   // right border
                } else {
                    #pragma unroll
                    for (int j = 0; j < 16; j++)
                        L[j] = fmaxf(L[j], 0.f);               // zfill OOB stays 0
                }
                if (ir <= 2) {
                    float a0 = w[3 * ir], a1 = w[3 * ir + 1], a2 = w[3 * ir + 2];
                    #pragma unroll
                    for (int j = 0; j < 8; j++)
                        s0a[j] = fmaf(a0, L[3 + j],
                                 fmaf(a1, L[4 + j], fmaf(a2, L[5 + j], s0a[j])));
                }
                if (ir >= 1) {
                    float b0 = w[3 * (ir - 1)], b1 = w[3 * (ir - 1) + 1],
                          b2 = w[3 * (ir - 1) + 2];
                    #pragma unroll
                    for (int j = 0; j < 8; j++)
                        s1a[j] = fmaf(b0, L[3 + j],
                                 fmaf(b1, L[4 + j], fmaf(b2, L[5 + j], s1a[j])));
                }
            }
            uint32_t h0w[4], h1w[4];
            #pragma unroll
            for (int jp = 0; jp < 4; jp++) {
                __half a0 = __float2half_rn(s0a[2 * jp]);
                __half a1 = __float2half_rn(s0a[2 * jp + 1]);
                __half b0 = __float2half_rn(s1a[2 * jp]);
                __half b1 = __float2half_rn(s1a[2 * jp + 1]);
                h0w[jp] = (uint32_t)__half_as_ushort(a0)
                        | ((uint32_t)__half_as_ushort(a1) << 16);
                h1w[jp] = (uint32_t)__half_as_ushort(b0)
                        | ((uint32_t)__half_as_ushort(b1) << 16);
            }
            uint32_t toff = ((s & 1) ? THI1_OFF : THI0_OFF)
                          + (uint32_t)cl * TSTRIDE + (uint32_t)(64 * ph2 + 16 * half);
            *(uint4*)(smb + toff) = make_uint4(h0w[0], h0w[1], h0w[2], h0w[3]);
            *(uint4*)(smb + toff + 32) = make_uint4(h1w[0], h1w[1], h1w[2], h1w[3]);
        } else {
            // ---- consumer: MMA(s-1); epilogue when a tile's chunk-3 MMA completes ----
            if (s > 0) {
                do_mma((s - 1) & 3, (s - 1) & 1);
                if (((s - 1) & 3) == 3) epilogue((s - 1) >> 2);
            }
        }
    }

    // ---- tail: MMA(last) + epilogue(last tile) ----
    __syncthreads();                   // last T writes complete
    if (wid >= 8) {
        do_mma(3, (smax - 1) & 1);
        epilogue(ntiles - 1);
    }
}

// ---------------- BN helpers ----------------
__global__ void bn_finalize(const float* __restrict__ sum, const float* __restrict__ sq,
                            const float* __restrict__ gamma, const float* __restrict__ beta,
                            float* __restrict__ scale, float* __restrict__ shift) {
    int c = threadIdx.x;
    float inv = 1.0f / NHW_F;
    float m = sum[c] * inv;
    float v = sq[c] * inv - m * m;
    float sc = gamma[c] * rsqrtf(v + EPSV);
    scale[c] = sc;
    shift[c] = beta[c] - m * sc;
}

__global__ void bn_apply(float* __restrict__ y, const float* __restrict__ scale,
                         const float* __restrict__ shift) {
    const int total4 = (NN * CCH * HH * WW) / 4;
    float4* p = (float4*)y;
    for (int i = blockIdx.x * blockDim.x + threadIdx.x; i < total4;
         i += gridDim.x * blockDim.x) {
        int c = (i >> 10) & (CCH - 1);
        float s = scale[c], t = shift[c];
        float4 v = p[i];
        v.x = fmaf(v.x, s, t); v.y = fmaf(v.y, s, t);
        v.z = fmaf(v.z, s, t); v.w = fmaf(v.w, s, t);
        p[i] = v;
    }
}

// ---------------- launch ----------------
extern "C" void kernel_launch(void* const* d_in, const int* in_sizes, int n_in,
                              void* d_out, int out_size) {
    const float* x      = (const float*)d_in[0];
    const float* dw1_w  = (const float*)d_in[1];
    const float* pw1_w  = (const float*)d_in[2];
    const float* gamma1 = (const float*)d_in[3];
    const float* beta1  = (const float*)d_in[4];
    const float* dw2_w  = (const float*)d_in[5];
    const float* pw2_w  = (const float*)d_in[6];
    const float* gamma2 = (const float*)d_in[7];
    const float* beta2  = (const float*)d_in[8];
    float* out = (float*)d_out;

    float *y1, *stats, *sc;
    unsigned char* wt;
    cudaGetSymbolAddress((void**)&y1, g_y1);
    cudaGetSymbolAddress((void**)&stats, g_stats);
    cudaGetSymbolAddress((void**)&sc, g_sc);
    cudaGetSymbolAddress((void**)&wt, g_wt);

    cudaFuncSetAttribute((const void*)conv_mma<false>,
                         cudaFuncAttributeMaxDynamicSharedMemorySize, SMEM_BYTES);
    cudaFuncSetAttribute((const void*)conv_mma<true>,
                         cudaFuncAttributeMaxDynamicSharedMemorySize, SMEM_BYTES);

    prep_w<<<64, 512>>>(pw1_w, pw2_w, wt, stats);

    conv_mma<false><<<GRID, 512, SMEM_BYTES>>>(x, dw1_w, wt, nullptr, nullptr,
                                               y1, stats, stats + CCH);
    bn_finalize<<<1, CCH>>>(stats, stats + CCH, gamma1, beta1, sc, sc + CCH);

    conv_mma<true><<<GRID, 512, SMEM_BYTES>>>(y1, dw2_w, wt + 32768, sc, sc + CCH,
                                              out, stats + 2 * CCH, stats + 3 * CCH);
    bn_finalize<<<1, CCH>>>(stats + 2 * CCH, stats + 3 * CCH, gamma2, beta2,
                            sc + 2 * CCH, sc + 3 * CCH);

    bn_apply<<<2048, 256>>>(out, sc + 2 * CCH, sc + 3 * CCH);
}

// round 15
// speedup vs baseline: 1.3255x; 1.0018x over previous
#include <cuda_runtime.h>
#include <cuda_fp16.h>
#include <cstdint>

// ---------------- problem constants ----------------
#define NN 32
#define CCH 128
#define HH 64
#define WW 64
#define NHW_F 131072.0f
#define EPSV 1e-5f
#define GRID 148                    // persistent CTAs (1 per SM)
#define NTILES_TOTAL 1024           // 32 images x 32 tiles

// ---------------- smem layout (byte offsets) ----------------
#define TSTRIDE 272                 // 17x16B segs -> LDSM conflict-free
#define WHI_OFF 0
#define THI0_OFF 34816              // 128*272
#define THI1_OFF 43520              // +32*272
#define XS0_OFF 52224
// XS: 32 channels x 10 rows x 128B rows, SW128-swizzled.
// Halo col h at float offset h+3 within the row (floats 3..20 used).
#define XCHB 1280u                  // 10 rows * 128 B per channel
#define XSBUF_BYTES 40960           // 32 * 1280
#define XS1_OFF (XS0_OFF + XSBUF_BYTES)     // 93184
#define RED_OFF (XS1_OFF + XSBUF_BYTES)     // 134144
#define SMEM_BYTES (RED_OFF + 2048)         // 136192

#define SWZ(b) ((b) ^ (((b) >> 3) & 0x70u))

// ---------------- device scratch ----------------
__device__ float g_y1[NN * CCH * HH * WW];
__device__ unsigned char g_wt[65536];       // 2 blocks x 32KB fp16 [o][c]
__device__ float g_stats[4 * CCH];
__device__ float g_sc[4 * CCH];

// ---------------- PTX helpers ----------------
__device__ __forceinline__ uint32_t smem_u32(const void* p) {
    uint32_t a;
    asm("{ .reg .u64 t; cvta.to.shared.u64 t, %1; cvt.u32.u64 %0, t; }" : "=r"(a) : "l"(p));
    return a;
}
__device__ __forceinline__ void ldsm_x4(uint32_t* r, uint32_t a) {
    asm volatile("ldmatrix.sync.aligned.m8n8.x4.shared.b16 {%0,%1,%2,%3}, [%4];"
                 : "=r"(r[0]), "=r"(r[1]), "=r"(r[2]), "=r"(r[3]) : "r"(a));
}
__device__ __forceinline__ void ldsmt_x4(uint32_t* r, uint32_t a) {
    asm volatile("ldmatrix.sync.aligned.m8n8.x4.trans.shared.b16 {%0,%1,%2,%3}, [%4];"
                 : "=r"(r[0]), "=r"(r[1]), "=r"(r[2]), "=r"(r[3]) : "r"(a));
}
__device__ __forceinline__ void mma16816h(float* d, const uint32_t* a, const uint32_t* b) {
    asm volatile("mma.sync.aligned.m16n8k16.row.col.f32.f16.f16.f32 "
                 "{%0,%1,%2,%3}, {%4,%5,%6,%7}, {%8,%9}, {%0,%1,%2,%3};"
                 : "+f"(d[0]), "+f"(d[1]), "+f"(d[2]), "+f"(d[3])
                 : "r"(a[0]), "r"(a[1]), "r"(a[2]), "r"(a[3]), "r"(b[0]), "r"(b[1]));
}
__device__ __forceinline__ void cp_async4(uint32_t dst, const void* src, uint32_t srcsz) {
    asm volatile("cp.async.ca.shared.global [%0], [%1], 4, %2;"
                 :: "r"(dst), "l"(src), "r"(srcsz) : "memory");
}
__device__ __forceinline__ void cp_async16(uint32_t dst, const void* src, uint32_t srcsz) {
    asm volatile("cp.async.cg.shared.global [%0], [%1], 16, %2;"
                 :: "r"(dst), "l"(src), "r"(srcsz) : "memory");
}
#define CP_COMMIT() asm volatile("cp.async.commit_group;" ::: "memory")
#define CP_WAIT0()  asm volatile("cp.async.wait_group 0;" ::: "memory")
#define BAR_MMA()   asm volatile("bar.sync 1, 256;" ::: "memory")

// ---------------- prep: pw weights to fp16; zero stats ----------------
__global__ void prep_w(const float* __restrict__ pw1, const float* __restrict__ pw2,
                       unsigned char* __restrict__ wt, float* __restrict__ stats) {
    int idx = blockIdx.x * blockDim.x + threadIdx.x;
    if (idx < 4 * CCH) stats[idx] = 0.f;
    if (idx >= 32768) return;
    int blk = idx >> 14;
    int w = idx & 16383;
    float v = (blk ? pw2 : pw1)[w];
    *(__half*)(wt + (uint32_t)blk * 32768u + (uint32_t)w * 2u) = __float2half_rn(v);
}

// ---------------- fused relu(+BN) -> dw3x3 -> HMMA(fp16) pointwise + stats ----------------
// Persistent, warp-specialized (8 producer / 8 consumer warps), SW128-swizzled halo.
template <bool PRE_BN>
__global__ __launch_bounds__(512, 1) void conv_mma(
    const float* __restrict__ in, const float* __restrict__ dww,
    const unsigned char* __restrict__ wt,
    const float* __restrict__ prescale, const float* __restrict__ preshift,
    float* __restrict__ out, float* __restrict__ osum, float* __restrict__ osq)
{
    extern __shared__ char smb[];
    const uint32_t base32 = smem_u32(smb);

    const int tid = threadIdx.x;
    const int wid = tid >> 5;
    const int lane = tid & 31;
    const int bx = blockIdx.x;
    const int ntiles = (NTILES_TOTAL - bx + GRID - 1) / GRID;
    const int smax = ntiles * 4;

    // ---- halo issue for stage s (tile = bx + (s>>2)*GRID, chunk = s&3) ----
    auto issue_halo = [&](int s) {
        const int t = bx + (s >> 2) * GRID;
        const int n = t >> 5;
        const int tl = t & 31;
        const int th0 = (tl >> 2) * 8;
        const int tw0 = (tl & 3) * 16;
        const int c0 = (s & 3) * 32;
        const uint32_t xsb = base32 + ((s & 1) ? XS1_OFF : XS0_OFF);
        // vector part: 32ch * 10r * 4 = 1280 16B copies (halo cols 1..16 at floats 4..19)
        #pragma unroll
        for (int u = 0; u < 3; u++) {
            int i = tid + u * 512;
            if (i < 1280) {
                int c = i / 40, rr = i - c * 40;
                int r = rr >> 2, f = rr & 3;
                int gh = th0 - 1 + r;
                bool ok = (unsigned)gh < (unsigned)HH;
                int ghc = ok ? gh : 0;
                const float* src = in + (((size_t)(n * CCH + c0 + c) * HH + ghc) * WW
                                         + tw0 + 4 * f);
                uint32_t lin = (uint32_t)c * XCHB + (uint32_t)r * 128u + 16u + 16u * f;
                cp_async16(xsb + SWZ(lin), src, ok ? 16u : 0u);
            }
        }
        // scalar part: edge cols h=0 (byte 12) and h=17 (byte 80): 640 copies
        #pragma unroll
        for (int u = 0; u < 2; u++) {
            int e = tid + u * 512;
            if (e < 640) {
                int c = e / 20, rr = e - c * 20;
                int r = rr >> 1, side = rr & 1;
                int gh = th0 - 1 + r;
                int gw = side ? (tw0 + 16) : (tw0 - 1);
                bool ok = ((unsigned)gh < (unsigned)HH) && ((unsigned)gw < (unsigned)WW);
                const float* src = ok ? in + (((size_t)(n * CCH + c0 + c) * HH + gh) * WW + gw)
                                      : in;
                uint32_t lin = (uint32_t)c * XCHB + (uint32_t)r * 128u + (side ? 80u : 12u);
                cp_async4(xsb + SWZ(lin), src, ok ? 4u : 0u);
            }
        }
        CP_COMMIT();
    };

    issue_halo(0);

    // ---- W copy into padded smem (once per CTA; overlaps stage-0 cp.async) ----
    {
        const float4* whi = (const float4*)wt;     // 2048 f4
        #pragma unroll
        for (int u = 0; u < 4; u++) {
            int i = tid + u * 512;
            int o = i >> 4, seg = i & 15;
            uint32_t off = (uint32_t)o * TSTRIDE + (uint32_t)seg * 16u;
            *(float4*)(smb + WHI_OFF + off) = whi[i];
        }
    }

    // ---- producer mapping: 8 threads/channel, thread m = one output row (16 cols) ----
    const int cl = (tid >> 3) & 31;
    const int m = tid & 7;             // output row 0..7
    float scs[4], shs[4];
    if (PRE_BN) {
        #pragma unroll
        for (int ch = 0; ch < 4; ch++) {
            scs[ch] = prescale[ch * 32 + cl];
            shs[ch] = preshift[ch * 32 + cl];
        }
    }

    // ---- consumer tiling: 8 warps, 32(o) x 64(px) each ----
    const int mw = (wid - 8) & 7;
    const int o0 = (mw & 3) * 32;
    const int pg = mw >> 2;
    const int p0 = pg * 64;
    const uint32_t aRow = (uint32_t)(o0 + (lane & 15)) * TSTRIDE + (uint32_t)(lane >> 4) * 16u;
    const uint32_t bRow = (uint32_t)(lane & 15) * TSTRIDE + (uint32_t)(p0 + (lane >> 4) * 8) * 2u;
    const uint32_t aHi0 = base32 + WHI_OFF + aRow;
    const uint32_t bT0 = base32 + THI0_OFF + bRow;
    const uint32_t bT1 = base32 + THI1_OFF + bRow;

    float d[2][8][4];
    #pragma unroll
    for (int i = 0; i < 2; i++)
        #pragma unroll
        for (int j = 0; j < 8; j++)
            #pragma unroll
            for (int r = 0; r < 4; r++) d[i][j][r] = 0.f;

    auto do_mma = [&](int chm, int buf) {
        const uint32_t bb = buf ? bT1 : bT0;
        #pragma unroll
        for (int kk2 = 0; kk2 < 2; kk2++) {
            const uint32_t ao = (uint32_t)(chm * 2 + kk2) * 32u;
            const uint32_t bo = (uint32_t)kk2 * (16u * TSTRIDE);
            uint32_t ah[2][4], bh[4][4];
            ldsm_x4(ah[0], aHi0 + ao);
            ldsm_x4(ah[1], aHi0 + ao + 16u * TSTRIDE);
            #pragma unroll
            for (int g = 0; g < 4; g++) ldsmt_x4(bh[g], bb + bo + (uint32_t)g * 32u);
            #pragma unroll
            for (int i = 0; i < 2; i++)
                #pragma unroll
                for (int g = 0; g < 4; g++)
                    #pragma unroll
                    for (int h = 0; h < 2; h++)
                        mma16816h(d[i][g * 2 + h], ah[i], &bh[g][h * 2]);
        }
    };

    // ---- epilogue for owned tile k (MMA warps only) ----
    auto epilogue = [&](int k) {
        const int t = bx + k * GRID;
        const int n = t >> 5;
        const int tl = t & 31;
        const int th0e = (tl >> 2) * 8;
        const int tw0e = (tl & 3) * 16;
        const int grp = lane >> 2, tg = lane & 3;
        float* redS = (float*)(smb + RED_OFF);       // 256 + 256 floats
        float* redQ = redS + 256;
        #pragma unroll
        for (int i = 0; i < 2; i++) {
            #pragma unroll
            for (int rh = 0; rh < 2; rh++) {
                int o = o0 + i * 16 + grp + rh * 8;
                float sv = 0.f, qv = 0.f;
                #pragma unroll
                for (int j = 0; j < 8; j++) {
                    int px = p0 + j * 8 + tg * 2;
                    float v0 = d[i][j][rh * 2], v1 = d[i][j][rh * 2 + 1];
                    *(float2*)(out + ((size_t)(n * CCH + o) * HH + th0e + (px >> 4)) * WW
                                     + tw0e + (px & 15)) = make_float2(v0, v1);
                    sv += v0 + v1;
                    qv = fmaf(v0, v0, fmaf(v1, v1, qv));
                }
                sv += __shfl_xor_sync(0xffffffffu, sv, 1);
                sv += __shfl_xor_sync(0xffffffffu, sv, 2);
                qv += __shfl_xor_sync(0xffffffffu, qv, 1);
                qv += __shfl_xor_sync(0xffffffffu, qv, 2);
                if (tg == 0) {
                    redS[o * 2 + pg] = sv;
                    redQ[o * 2 + pg] = qv;
                }
            }
        }
        #pragma unroll
        for (int i = 0; i < 2; i++)
            #pragma unroll
            for (int j = 0; j < 8; j++)
                #pragma unroll
                for (int r = 0; r < 4; r++) d[i][j][r] = 0.f;
        BAR_MMA();
        int c = tid - 256;
        if (c >= 0 && c < CCH) {
            atomicAdd(&osum[c], redS[c * 2] + redS[c * 2 + 1]);
            atomicAdd(&osq[c], redQ[c * 2] + redQ[c * 2 + 1]);
        }
    };

    for (int s = 0; s < smax; s++) {
        const int t = bx + (s >> 2) * GRID;
        const int tl = t & 31;
        const int th0 = (tl >> 2) * 8;
        const int tw0 = (tl & 3) * 16;
        const int ch = s & 3;
        const int c0 = ch * 32;
        const uint32_t xsoff = (s & 1) ? XS1_OFF : XS0_OFF;

        CP_WAIT0();        // halo(s) arrived
        __syncthreads();   // phase s-1 fully done (T[(s-1)&1] written, XS[(s+1)&1] free)

        if (s + 1 < smax) issue_halo(s + 1);

        if (wid < 8) {
            // ---- producer: depthwise(s), one row x 16 cols, swizzled conflict-free ----
            const float* wp = dww + (c0 + cl) * 9;
            float w[9];
            #pragma unroll
            for (int k = 0; k < 9; k++) w[k] = wp[k];
            const float scv = PRE_BN ? scs[ch] : 1.f;
            const float shv = PRE_BN ? shs[ch] : 0.f;
            const uint32_t chbase = (uint32_t)cl * XCHB;
            float sacc[16];
            #pragma unroll
            for (int c = 0; c < 16; c++) sacc[c] = 0.f;
            #pragma unroll
            for (int ir = 0; ir < 3; ir++) {
                const int lr = m + ir;          // halo row 0..9
                const int gh = th0 - 1 + lr;
                const bool rowok = (unsigned)gh < (unsigned)HH;
                if (PRE_BN && !rowok) continue; // OOB row contributes 0
                float L[24];
                #pragma unroll
                for (int k = 0; k < 6; k++) {
                    uint32_t lin = chbase + (uint32_t)lr * 128u + (uint32_t)k * 16u;
                    float4 v = *(const float4*)(smb + xsoff + SWZ(lin));
                    L[4 * k + 0] = v.x; L[4 * k + 1] = v.y;
                    L[4 * k + 2] = v.z; L[4 * k + 3] = v.w;
                }
                if (PRE_BN) {
                    #pragma unroll
                    for (int j = 3; j < 21; j++)
                        L[j] = fmaxf(fmaf(L[j], scv, shv), 0.f);
                    if (tw0 == 0) L[3] = 0.f;       // left border (halo col 0 OOB)
                    if (tw0 == 48) L[20] = 0.f;     // right border (halo col 17 OOB)
                } else {
                    #pragma unroll
                    for (int j = 3; j < 21; j++)
                        L[j] = fmaxf(L[j], 0.f);    // zfill OOB stays 0
                }
                float a0 = w[3 * ir], a1 = w[3 * ir + 1], a2 = w[3 * ir + 2];
                #pragma unroll
                for (int c = 0; c < 16; c++)
                    sacc[c] = fmaf(a0, L[3 + c],
                              fmaf(a1, L[4 + c], fmaf(a2, L[5 + c], sacc[c])));
            }
            uint32_t hw[8];
            #pragma unroll
            for (int jp = 0; jp < 8; jp++) {
                __half h0 = __float2half_rn(sacc[2 * jp]);
                __half h1 = __float2half_rn(sacc[2 * jp + 1]);
                hw[jp] = (uint32_t)__half_as_ushort(h0)
                       | ((uint32_t)__half_as_ushort(h1) << 16);
            }
            uint32_t toff = ((s & 1) ? THI1_OFF : THI0_OFF)
                          + (uint32_t)cl * TSTRIDE + (uint32_t)m * 32u;
            *(uint4*)(smb + toff) = make_uint4(hw[0], hw[1], hw[2], hw[3]);
            *(uint4*)(smb + toff + 16) = make_uint4(hw[4], hw[5], hw[6], hw[7]);
        } else {
            // ---- consumer: MMA(s-1); epilogue when a tile's chunk-3 MMA completes ----
            if (s > 0) {
                do_mma((s - 1) & 3, (s - 1) & 1);
                if (((s - 1) & 3) == 3) epilogue((s - 1) >> 2);
            }
        }
    }

    // ---- tail: MMA(last) + epilogue(last tile) ----
    __syncthreads();                   // last T writes complete
    if (wid >= 8) {
        do_mma(3, (smax - 1) & 1);
        epilogue(ntiles - 1);
    }
}

// ---------------- BN helpers ----------------
__global__ void bn_finalize(const float* __restrict__ sum, const float* __restrict__ sq,
                            const float* __restrict__ gamma, const float* __restrict__ beta,
                            float* __restrict__ scale, float* __restrict__ shift) {
    int c = threadIdx.x;
    float inv = 1.0f / NHW_F;
    float m = sum[c] * inv;
    float v = sq[c] * inv - m * m;
    float sc = gamma[c] * rsqrtf(v + EPSV);
    scale[c] = sc;
    shift[c] = beta[c] - m * sc;
}

__global__ void bn_apply(float* __restrict__ y, const float* __restrict__ scale,
                         const float* __restrict__ shift) {
    const int total4 = (NN * CCH * HH * WW) / 4;
    float4* p = (float4*)y;
    for (int i = blockIdx.x * blockDim.x + threadIdx.x; i < total4;
         i += gridDim.x * blockDim.x) {
        int c = (i >> 10) & (CCH - 1);
        float s = scale[c], t = shift[c];
        float4 v = p[i];
        v.x = fmaf(v.x, s, t); v.y = fmaf(v.y, s, t);
        v.z = fmaf(v.z, s, t); v.w = fmaf(v.w, s, t);
        p[i] = v;
    }
}

// ---------------- launch ----------------
extern "C" void kernel_launch(void* const* d_in, const int* in_sizes, int n_in,
                              void* d_out, int out_size) {
    const float* x      = (const float*)d_in[0];
    const float* dw1_w  = (const float*)d_in[1];
    const float* pw1_w  = (const float*)d_in[2];
    const float* gamma1 = (const float*)d_in[3];
    const float* beta1  = (const float*)d_in[4];
    const float* dw2_w  = (const float*)d_in[5];
    const float* pw2_w  = (const float*)d_in[6];
    const float* gamma2 = (const float*)d_in[7];
    const float* beta2  = (const float*)d_in[8];
    float* out = (float*)d_out;

    float *y1, *stats, *sc;
    unsigned char* wt;
    cudaGetSymbolAddress((void**)&y1, g_y1);
    cudaGetSymbolAddress((void**)&stats, g_stats);
    cudaGetSymbolAddress((void**)&sc, g_sc);
    cudaGetSymbolAddress((void**)&wt, g_wt);

    cudaFuncSetAttribute((const void*)conv_mma<false>,
                         cudaFuncAttributeMaxDynamicSharedMemorySize, SMEM_BYTES);
    cudaFuncSetAttribute((const void*)conv_mma<true>,
                         cudaFuncAttributeMaxDynamicSharedMemorySize, SMEM_BYTES);

    prep_w<<<64, 512>>>(pw1_w, pw2_w, wt, stats);

    conv_mma<false><<<GRID, 512, SMEM_BYTES>>>(x, dw1_w, wt, nullptr, nullptr,
                                               y1, stats, stats + CCH);
    bn_finalize<<<1, CCH>>>(stats, stats + CCH, gamma1, beta1, sc, sc + CCH);

    conv_mma<true><<<GRID, 512, SMEM_BYTES>>>(y1, dw2_w, wt + 32768, sc, sc + CCH,
                                              out, stats + 2 * CCH, stats + 3 * CCH);
    bn_finalize<<<1, CCH>>>(stats + 2 * CCH, stats + 3 * CCH, gamma2, beta2,
                            sc + 2 * CCH, sc + 3 * CCH);

    bn_apply<<<2048, 256>>>(out, sc + 2 * CCH, sc + 3 * CCH);
}